// round 3
// baseline (speedup 1.0000x reference)
#include <cuda_runtime.h>
#include <math.h>

#define SQ 2048
#define NB 8
#define HDIM 768
#define HD 384
#define NG 1536
#define NT 64
#define NU 32

// ---------------- device scratch (static, no runtime alloc) ----------------
__device__ float    g_xproj[2u * SQ * NB * NG];   // [dir][t][b][gate_row]  ~201 MB
__device__ float    g_hbuf [2 * 2 * NB * HD];     // [dir][buf][b][j]
__device__ unsigned g_flag [2 * 64];              // per (dir, cta) step flag
__device__ float    g_mp   [NB * NU * HDIM];      // [b][u][h] pooled features
__device__ float    g_emb  [NB * NU * HDIM];      // [b][u][h] routed embeddings

// ---------------- flag reset (graph replays must be deterministic) ---------
__global__ void k_reset()
{
    int i = threadIdx.x;
    if (i < 128) g_flag[i] = 0u;
}

// ---------------- K1: input projection GEMM (both directions) --------------
// xproj[dir][t][b][n] = X[b, s, :] @ Wih_dir^T + bih + bhh   (t = s or S-1-s)
// (R1 version — known good)
__global__ void __launch_bounds__(256) k_gemm(
    const float* __restrict__ X,
    const float* __restrict__ Wf, const float* __restrict__ Wb,
    const float* __restrict__ bihf, const float* __restrict__ bhhf,
    const float* __restrict__ bihb, const float* __restrict__ bhhb)
{
    const int dir = blockIdx.z;
    const float* W = dir ? Wb : Wf;
    const int n0 = blockIdx.x * 128;
    const int m0 = blockIdx.y * 128;

    __shared__ float As[8][128];
    __shared__ float Bs[8][128];

    const int tid = threadIdx.x;
    const int lr = tid >> 1, lh = tid & 1;   // loader: row, half (4 floats)
    const int tx = tid & 15, ty = tid >> 4;  // compute: 16x16 thread grid

    float acc[8][8];
#pragma unroll
    for (int i = 0; i < 8; i++)
#pragma unroll
        for (int j = 0; j < 8; j++) acc[i][j] = 0.f;

    const float* xptr = X + (m0 + lr) * 768 + lh * 4;
    const float* wptr = W + (n0 + lr) * 768 + lh * 4;

    for (int kt = 0; kt < 768; kt += 8) {
        float4 av = *(const float4*)(xptr + kt);
        float4 bv = *(const float4*)(wptr + kt);
        __syncthreads();
        As[lh * 4 + 0][lr] = av.x; As[lh * 4 + 1][lr] = av.y;
        As[lh * 4 + 2][lr] = av.z; As[lh * 4 + 3][lr] = av.w;
        Bs[lh * 4 + 0][lr] = bv.x; Bs[lh * 4 + 1][lr] = bv.y;
        Bs[lh * 4 + 2][lr] = bv.z; Bs[lh * 4 + 3][lr] = bv.w;
        __syncthreads();
#pragma unroll
        for (int k = 0; k < 8; k++) {
            float a[8], b[8];
            *(float4*)(a)     = *(const float4*)&As[k][ty * 8];
            *(float4*)(a + 4) = *(const float4*)&As[k][ty * 8 + 4];
            *(float4*)(b)     = *(const float4*)&Bs[k][tx * 8];
            *(float4*)(b + 4) = *(const float4*)&Bs[k][tx * 8 + 4];
#pragma unroll
            for (int i = 0; i < 8; i++)
#pragma unroll
                for (int j = 0; j < 8; j++)
                    acc[i][j] = fmaf(a[i], b[j], acc[i][j]);
        }
    }

    const float* bi = dir ? bihb : bihf;
    const float* bh = dir ? bhhb : bhhf;
    float bias[8];
#pragma unroll
    for (int j = 0; j < 8; j++) {
        int n = n0 + tx * 8 + j;
        bias[j] = bi[n] + bh[n];
    }
#pragma unroll
    for (int i = 0; i < 8; i++) {
        int m = m0 + ty * 8 + i;
        int s = m & 2047, bb = m >> 11;
        int t = dir ? (2047 - s) : s;
        float* o = g_xproj + ((((dir * SQ + t) * NB + bb) * NG) + n0 + tx * 8);
        float4 v0, v1;
        v0.x = acc[i][0] + bias[0]; v0.y = acc[i][1] + bias[1];
        v0.z = acc[i][2] + bias[2]; v0.w = acc[i][3] + bias[3];
        v1.x = acc[i][4] + bias[4]; v1.y = acc[i][5] + bias[5];
        v1.z = acc[i][6] + bias[6]; v1.w = acc[i][7] + bias[7];
        *(float4*)(o)     = v0;
        *(float4*)(o + 4) = v1;
    }
}

// ---------------- K2: persistent BiLSTM recurrence + fused segment max -----
// 128 CTAs: dir = bx>>6, slice r = bx&63 owns units j in [6r, 6r+6).
// 8 warps = 4 gate-groups x 2 batch-groups; warp (g, bg) computes gate g of
// 6 units for batches [4bg, 4bg+4). k interleaved per lane (k = lane + 32q):
// conflict-free scalar LDS, no cross-warp redundancy in the batch dimension.
__global__ void __launch_bounds__(256, 1) k_lstm(
    const float* __restrict__ Whhf, const float* __restrict__ Whhb,
    const int* __restrict__ utter)
{
    const int dir = blockIdx.x >> 6;
    const int r   = blockIdx.x & 63;
    const int j0  = r * 6;
    const float* Whh = dir ? Whhb : Whhf;
    const int tid = threadIdx.x;
    const int wid = tid >> 5, lane = tid & 31;
    const int gate = wid >> 1;       // 0..3
    const int bg   = wid & 1;        // 0..1 -> batches [4bg, 4bg+4)

    __shared__ __align__(16) float h_s[NB][HD];   // current hidden, all batches
    __shared__ float gate_s[24][NB];              // rows = gate*6 + unit
    __shared__ float segmax_s[NB][33][6];         // fused per-utterance max

    for (int i = tid; i < NB * HD; i += 256) (&h_s[0][0])[i] = 0.f;
    for (int i = tid; i < NB * 33 * 6; i += 256) (&segmax_s[0][0][0])[i] = 0.f;

    // weights: w[i][q] = Whh[(gate*HD + j0 + i) * HD + lane + 32q]
    float w[6][12];
#pragma unroll
    for (int i = 0; i < 6; i++) {
        const float* wr = Whh + (gate * HD + j0 + i) * HD + lane;
#pragma unroll
        for (int q = 0; q < 12; q++) w[i][q] = wr[32 * q];
    }

    const int jj_a = tid / 8, b_a = tid % 8;      // activation thread (tid<48)
    float c_state = 0.f;
    unsigned* flags = g_flag + dir * 64;
    float* hbase = g_hbuf + dir * 2 * NB * HD;

    __syncthreads();

    for (int t = 0; t < SQ; t++) {
        // prefetch xproj + utterance id (hidden under the FMA phase)
        float xp0 = 0.f, xp1 = 0.f, xp2 = 0.f, xp3 = 0.f;
        int useg = 0;
        if (tid < 48) {
            int pos = dir ? (SQ - 1 - t) : t;
            const float* xb = g_xproj + ((((dir * SQ + t) * NB + b_a) * NG) + j0 + jj_a);
            xp0 = xb[0]; xp1 = xb[HD]; xp2 = xb[2 * HD]; xp3 = xb[3 * HD];
            int u = utter[b_a * SQ + pos];
            useg = u > 0 ? u : 0;
        }

        // gate partials: 6 units x 4 batches, k = lane + 32q (q = 0..11)
        float p[6][4];
#pragma unroll
        for (int i = 0; i < 6; i++)
#pragma unroll
            for (int b = 0; b < 4; b++) p[i][b] = 0.f;
#pragma unroll
        for (int q = 0; q < 12; q++) {
            int k = lane + 32 * q;
            float h0 = h_s[bg * 4 + 0][k];
            float h1 = h_s[bg * 4 + 1][k];
            float h2 = h_s[bg * 4 + 2][k];
            float h3 = h_s[bg * 4 + 3][k];
#pragma unroll
            for (int i = 0; i < 6; i++) {
                float wv = w[i][q];
                p[i][0] = fmaf(wv, h0, p[i][0]);
                p[i][1] = fmaf(wv, h1, p[i][1]);
                p[i][2] = fmaf(wv, h2, p[i][2]);
                p[i][3] = fmaf(wv, h3, p[i][3]);
            }
        }
#pragma unroll
        for (int i = 0; i < 6; i++)
#pragma unroll
            for (int b = 0; b < 4; b++) {
                float v = p[i][b];
                v += __shfl_xor_sync(0xffffffffu, v, 16);
                v += __shfl_xor_sync(0xffffffffu, v, 8);
                v += __shfl_xor_sync(0xffffffffu, v, 4);
                v += __shfl_xor_sync(0xffffffffu, v, 2);
                v += __shfl_xor_sync(0xffffffffu, v, 1);
                if (lane == 0) gate_s[gate * 6 + i][bg * 4 + b] = v;
            }
        __syncthreads();

        // activation + publish + fused segment max
        if (tid < 48) {
            float vi = gate_s[jj_a][b_a]      + xp0;
            float vf = gate_s[6 + jj_a][b_a]  + xp1;
            float vg = gate_s[12 + jj_a][b_a] + xp2;
            float vo = gate_s[18 + jj_a][b_a] + xp3;
            float si = 1.f / (1.f + expf(-vi));
            float sf = 1.f / (1.f + expf(-vf));
            float so = 1.f / (1.f + expf(-vo));
            c_state = sf * c_state + si * tanhf(vg);
            float h = so * tanhf(c_state);
            __stcg(hbase + (t & 1) * NB * HD + b_a * HD + j0 + jj_a, h);
            float* sm = &segmax_s[b_a][useg][jj_a];
            *sm = fmaxf(*sm, h);
        }
        __syncthreads();

        // inter-CTA barrier: release-store own flag, 2 warps poll 1 flag/lane
        if (tid == 0) {
            asm volatile("st.release.gpu.global.u32 [%0], %1;"
                         :: "l"(flags + r), "r"((unsigned)(t + 1)) : "memory");
        }
        if (wid < 2) {
            unsigned tgt = (unsigned)(t + 1);
            const unsigned* fp = flags + wid * 32 + lane;
            unsigned v;
            do {
                asm volatile("ld.acquire.gpu.global.u32 %0, [%1];"
                             : "=r"(v) : "l"(fp) : "memory");
            } while (!__all_sync(0xffffffffu, v >= tgt));
        }
        __syncthreads();

        // pull the full broadcast hidden state (L2, bypass L1)
        {
            const float4* src = (const float4*)(hbase + (t & 1) * NB * HD);
            float4* dst = (float4*)(&h_s[0][0]);
            for (int i = tid; i < NB * HD / 4; i += 256)
                dst[i] = __ldcg(src + i);
        }
        __syncthreads();
    }

    // emit mp[b][u][dir*384 + j] = max(segmax, 0)  (accumulator init was 0)
    if (tid < 48) {
        for (int u = 1; u <= NU; u++)
            g_mp[(b_a * NU + (u - 1)) * HDIM + dir * HD + j0 + jj_a] =
                segmax_s[b_a][u][jj_a];
    }
}

// ---------------- K3: topic softmax routing ---------------------------------
__global__ void __launch_bounds__(256) k_route(
    const float* __restrict__ tw, const float* __restrict__ tb,
    const float* __restrict__ table)
{
    const int b = blockIdx.x >> 5;
    const int u = blockIdx.x & 31;
    __shared__ float mp_s[768];
    __shared__ float lp_s[4][64];
    __shared__ float l_s[64], e_s[64];
    const int tid = threadIdx.x;
    const float* mpr = g_mp + (b * NU + u) * HDIM;
    for (int i = tid; i < 192; i += 256)
        ((float4*)mp_s)[i] = ((const float4*)mpr)[i];
    __syncthreads();
    {
        const int topic = tid & 63, slice = tid >> 6;
        float acc = 0.f;
        const float* wr = tw + topic * 768 + slice * 192;
        const float* ms = mp_s + slice * 192;
        for (int k = 0; k < 192; k += 4) {
            float4 wv = *(const float4*)(wr + k);
            acc = fmaf(wv.x, ms[k], acc);
            acc = fmaf(wv.y, ms[k + 1], acc);
            acc = fmaf(wv.z, ms[k + 2], acc);
            acc = fmaf(wv.w, ms[k + 3], acc);
        }
        lp_s[slice][topic] = acc;
    }
    __syncthreads();
    if (tid < 64)
        l_s[tid] = lp_s[0][tid] + lp_s[1][tid] + lp_s[2][tid] + lp_s[3][tid] + tb[tid];
    __syncthreads();
    if (tid < 64) {
        float mx = -1e30f;
        for (int i = 0; i < 64; i++) mx = fmaxf(mx, l_s[i]);
        e_s[tid] = expf(l_s[tid] - mx);
    }
    __syncthreads();
    float ssum = 0.f;
    for (int i = 0; i < 64; i++) ssum += e_s[i];
    float inv = 1.f / ssum;
    for (int h = tid; h < 768; h += 256) {
        float acc = 0.f;
        for (int tt = 0; tt < 64; tt++)
            acc = fmaf(e_s[tt], table[tt * 768 + h], acc);
        g_emb[(b * NU + u) * HDIM + h] = acc * inv;
    }
}

// ---------------- K4: scatter back to token positions -----------------------
__global__ void __launch_bounds__(256) k_scatter(
    const int* __restrict__ utter, float* __restrict__ out)
{
    int v = blockIdx.x * 256 + threadIdx.x;   // one float4 per thread, exact grid
    int m = v / 192;                          // (b, s)
    int h4 = v - m * 192;
    int u = __ldg(utter + m);
    float4 o = make_float4(0.f, 0.f, 0.f, 0.f);
    if (u != 0) {
        int idx = u > 0 ? u - 1 : -u - 1;
        if (idx > 31) idx = 31;
        int bb = m >> 11;
        float4 gv = *(const float4*)(g_emb + (bb * NU + idx) * HDIM + h4 * 4);
        float sc = u > 0 ? 1.f : 2.f;
        o.x = gv.x * sc; o.y = gv.y * sc; o.z = gv.z * sc; o.w = gv.w * sc;
    }
    ((float4*)out)[v] = o;
}

// ---------------- launch -----------------------------------------------------
extern "C" void kernel_launch(void* const* d_in, const int* in_sizes, int n_in,
                              void* d_out, int out_size)
{
    const float* X     = (const float*)d_in[0];
    const float* Wihf  = (const float*)d_in[1];
    const float* Whhf  = (const float*)d_in[2];
    const float* bihf  = (const float*)d_in[3];
    const float* bhhf  = (const float*)d_in[4];
    const float* Wihb  = (const float*)d_in[5];
    const float* Whhb  = (const float*)d_in[6];
    const float* bihb  = (const float*)d_in[7];
    const float* bhhb  = (const float*)d_in[8];
    const float* tw    = (const float*)d_in[9];
    const float* tb    = (const float*)d_in[10];
    const float* table = (const float*)d_in[11];
    const int*   utter = (const int*)d_in[12];

    k_reset<<<1, 128>>>();
    k_gemm<<<dim3(12, 128, 2), 256>>>(X, Wihf, Wihb, bihf, bhhf, bihb, bhhb);
    k_lstm<<<128, 256>>>(Whhf, Whhb, utter);
    k_route<<<256, 256>>>(tw, tb, table);
    k_scatter<<<12288, 256>>>(utter, (float*)d_out);
}

// round 4
// speedup vs baseline: 2.1012x; 2.1012x over previous
#include <cuda_runtime.h>
#include <math.h>

#define SQ 2048
#define NB 8
#define HDIM 768
#define HD 384
#define NG 1536
#define NT 64
#define NU 32

// ---------------- device scratch (static, no runtime alloc) ----------------
__device__ float    g_xproj[2u * SQ * NB * NG];   // [dir][t][b][gate_row]  ~201 MB
__device__ float    g_hbuf [2 * 2 * NB * HD];     // [dir][buf][b][j]
__device__ unsigned g_flag [2 * 64 * 32];         // one 128B line per (dir, cta)
__device__ float    g_mp   [NB * NU * HDIM];      // [b][u][h] pooled features
__device__ float    g_emb  [NB * NU * HDIM];      // [b][u][h] routed embeddings

// ---------------- flag reset (graph replays must be deterministic) ---------
__global__ void k_reset()
{
    int i = blockIdx.x * 256 + threadIdx.x;
    if (i < 2 * 64 * 32) g_flag[i] = 0u;
}

// ---------------- K1: input projection GEMM (both directions) --------------
// xproj[dir][t][b][n] = X[b, s, :] @ Wih_dir^T + bih + bhh   (t = s or S-1-s)
// (R1 version — known good)
__global__ void __launch_bounds__(256) k_gemm(
    const float* __restrict__ X,
    const float* __restrict__ Wf, const float* __restrict__ Wb,
    const float* __restrict__ bihf, const float* __restrict__ bhhf,
    const float* __restrict__ bihb, const float* __restrict__ bhhb)
{
    const int dir = blockIdx.z;
    const float* W = dir ? Wb : Wf;
    const int n0 = blockIdx.x * 128;
    const int m0 = blockIdx.y * 128;

    __shared__ float As[8][128];
    __shared__ float Bs[8][128];

    const int tid = threadIdx.x;
    const int lr = tid >> 1, lh = tid & 1;   // loader: row, half (4 floats)
    const int tx = tid & 15, ty = tid >> 4;  // compute: 16x16 thread grid

    float acc[8][8];
#pragma unroll
    for (int i = 0; i < 8; i++)
#pragma unroll
        for (int j = 0; j < 8; j++) acc[i][j] = 0.f;

    const float* xptr = X + (m0 + lr) * 768 + lh * 4;
    const float* wptr = W + (n0 + lr) * 768 + lh * 4;

    for (int kt = 0; kt < 768; kt += 8) {
        float4 av = *(const float4*)(xptr + kt);
        float4 bv = *(const float4*)(wptr + kt);
        __syncthreads();
        As[lh * 4 + 0][lr] = av.x; As[lh * 4 + 1][lr] = av.y;
        As[lh * 4 + 2][lr] = av.z; As[lh * 4 + 3][lr] = av.w;
        Bs[lh * 4 + 0][lr] = bv.x; Bs[lh * 4 + 1][lr] = bv.y;
        Bs[lh * 4 + 2][lr] = bv.z; Bs[lh * 4 + 3][lr] = bv.w;
        __syncthreads();
#pragma unroll
        for (int k = 0; k < 8; k++) {
            float a[8], b[8];
            *(float4*)(a)     = *(const float4*)&As[k][ty * 8];
            *(float4*)(a + 4) = *(const float4*)&As[k][ty * 8 + 4];
            *(float4*)(b)     = *(const float4*)&Bs[k][tx * 8];
            *(float4*)(b + 4) = *(const float4*)&Bs[k][tx * 8 + 4];
#pragma unroll
            for (int i = 0; i < 8; i++)
#pragma unroll
                for (int j = 0; j < 8; j++)
                    acc[i][j] = fmaf(a[i], b[j], acc[i][j]);
        }
    }

    const float* bi = dir ? bihb : bihf;
    const float* bh = dir ? bhhb : bhhf;
    float bias[8];
#pragma unroll
    for (int j = 0; j < 8; j++) {
        int n = n0 + tx * 8 + j;
        bias[j] = bi[n] + bh[n];
    }
#pragma unroll
    for (int i = 0; i < 8; i++) {
        int m = m0 + ty * 8 + i;
        int s = m & 2047, bb = m >> 11;
        int t = dir ? (2047 - s) : s;
        float* o = g_xproj + ((((dir * SQ + t) * NB + bb) * NG) + n0 + tx * 8);
        float4 v0, v1;
        v0.x = acc[i][0] + bias[0]; v0.y = acc[i][1] + bias[1];
        v0.z = acc[i][2] + bias[2]; v0.w = acc[i][3] + bias[3];
        v1.x = acc[i][4] + bias[4]; v1.y = acc[i][5] + bias[5];
        v1.z = acc[i][6] + bias[6]; v1.w = acc[i][7] + bias[7];
        *(float4*)(o)     = v0;
        *(float4*)(o + 4) = v1;
    }
}

// ---------------- K2: persistent BiLSTM recurrence + fused segment max -----
// 128 CTAs: dir = bx>>6, slice r = bx&63 owns j in [6r, 6r+6), all 4 gates,
// all 8 batches. Compute layout identical to R1 (fastest measured). Barrier:
// per-CTA flag padded to a full 128B line (distinct L2 slices), release-store
// arrive, 2 warps poll 1 line/lane with acquire loads.
__global__ void __launch_bounds__(256, 1) k_lstm(
    const float* __restrict__ Whhf, const float* __restrict__ Whhb,
    const int* __restrict__ utter)
{
    const int dir = blockIdx.x >> 6;
    const int r   = blockIdx.x & 63;
    const int j0  = r * 6;
    const float* Whh = dir ? Whhb : Whhf;
    const int tid = threadIdx.x;
    const int wid = tid >> 5, lane = tid & 31;

    __shared__ __align__(16) float h_s[NB][HD];   // current hidden, all batches
    __shared__ float gate_s[24][NB];              // Whh*h partial sums
    __shared__ float segmax_s[NB][33][6];         // fused per-utterance max

    for (int i = tid; i < NB * HD; i += 256) (&h_s[0][0])[i] = 0.f;
    for (int i = tid; i < NB * 33 * 6; i += 256) (&segmax_s[0][0][0])[i] = 0.f;

    // warp wid owns rows 3*wid..3*wid+2 (row lr -> gate g=lr/6, unit jj=lr%6)
    float w[3][12];
#pragma unroll
    for (int i = 0; i < 3; i++) {
        int lrw = wid * 3 + i;
        int g = lrw / 6, jj = lrw % 6;
        const float* wr = Whh + (g * HD + j0 + jj) * HD;
#pragma unroll
        for (int q = 0; q < 3; q++) {
            float4 v = *(const float4*)(wr + q * 128 + lane * 4);
            w[i][q * 4 + 0] = v.x; w[i][q * 4 + 1] = v.y;
            w[i][q * 4 + 2] = v.z; w[i][q * 4 + 3] = v.w;
        }
    }

    const int jj_a = tid / 8, b_a = tid % 8;      // activation thread (tid<48)
    float c_state = 0.f;
    unsigned* flags = g_flag + dir * 64 * 32;     // line r at flags + r*32
    float* hbase = g_hbuf + dir * 2 * NB * HD;

    __syncthreads();

    for (int t = 0; t < SQ; t++) {
        // prefetch xproj + utterance id (hidden under the FMA phase)
        float xp0 = 0.f, xp1 = 0.f, xp2 = 0.f, xp3 = 0.f;
        int useg = 0;
        if (tid < 48) {
            int pos = dir ? (SQ - 1 - t) : t;
            const float* xb = g_xproj + ((((dir * SQ + t) * NB + b_a) * NG) + j0 + jj_a);
            xp0 = xb[0]; xp1 = xb[HD]; xp2 = xb[2 * HD]; xp3 = xb[3 * HD];
            int u = utter[b_a * SQ + pos];
            useg = u > 0 ? u : 0;
        }

        // gate partials: 3 rows x 8 batches, 12 k per lane (R1 layout)
        float p[3][8];
#pragma unroll
        for (int i = 0; i < 3; i++)
#pragma unroll
            for (int b = 0; b < 8; b++) p[i][b] = 0.f;
#pragma unroll
        for (int b = 0; b < 8; b++) {
            float4 h0 = *(const float4*)&h_s[b][lane * 4];
            float4 h1 = *(const float4*)&h_s[b][128 + lane * 4];
            float4 h2 = *(const float4*)&h_s[b][256 + lane * 4];
#pragma unroll
            for (int i = 0; i < 3; i++) {
                float s = p[i][b];
                s = fmaf(w[i][0], h0.x, s);  s = fmaf(w[i][1], h0.y, s);
                s = fmaf(w[i][2], h0.z, s);  s = fmaf(w[i][3], h0.w, s);
                s = fmaf(w[i][4], h1.x, s);  s = fmaf(w[i][5], h1.y, s);
                s = fmaf(w[i][6], h1.z, s);  s = fmaf(w[i][7], h1.w, s);
                s = fmaf(w[i][8], h2.x, s);  s = fmaf(w[i][9], h2.y, s);
                s = fmaf(w[i][10], h2.z, s); s = fmaf(w[i][11], h2.w, s);
                p[i][b] = s;
            }
        }
#pragma unroll
        for (int i = 0; i < 3; i++)
#pragma unroll
            for (int b = 0; b < 8; b++) {
                float v = p[i][b];
                v += __shfl_xor_sync(0xffffffffu, v, 16);
                v += __shfl_xor_sync(0xffffffffu, v, 8);
                v += __shfl_xor_sync(0xffffffffu, v, 4);
                v += __shfl_xor_sync(0xffffffffu, v, 2);
                v += __shfl_xor_sync(0xffffffffu, v, 1);
                if (lane == 0) gate_s[wid * 3 + i][b] = v;
            }
        __syncthreads();

        // activation + publish + fused segment max (MUFU approx on the
        // serial critical path; error ~2^-11 << 1e-3 budget)
        if (tid < 48) {
            float vi = gate_s[jj_a][b_a]      + xp0;
            float vf = gate_s[6 + jj_a][b_a]  + xp1;
            float vg = gate_s[12 + jj_a][b_a] + xp2;
            float vo = gate_s[18 + jj_a][b_a] + xp3;
            float si = 1.f / (1.f + __expf(-vi));
            float sf = 1.f / (1.f + __expf(-vf));
            float so = 1.f / (1.f + __expf(-vo));
            float tg, tc;
            asm("tanh.approx.f32 %0, %1;" : "=f"(tg) : "f"(vg));
            c_state = sf * c_state + si * tg;
            asm("tanh.approx.f32 %0, %1;" : "=f"(tc) : "f"(c_state));
            float h = so * tc;
            __stcg(hbase + (t & 1) * NB * HD + b_a * HD + j0 + jj_a, h);
            float* sm = &segmax_s[b_a][useg][jj_a];
            *sm = fmaxf(*sm, h);
        }
        __syncthreads();

        // inter-CTA barrier: release-store own line, poll one line per lane
        if (tid == 0) {
            asm volatile("st.release.gpu.global.u32 [%0], %1;"
                         :: "l"(flags + r * 32), "r"((unsigned)(t + 1)) : "memory");
        }
        if (wid < 2) {
            unsigned tgt = (unsigned)(t + 1);
            const unsigned* fp = flags + (wid * 32 + lane) * 32;
            unsigned v;
            do {
                asm volatile("ld.acquire.gpu.global.u32 %0, [%1];"
                             : "=r"(v) : "l"(fp) : "memory");
            } while (!__all_sync(0xffffffffu, v >= tgt));
        }
        __syncthreads();

        // pull the full broadcast hidden state (L2, bypass L1)
        {
            const float4* src = (const float4*)(hbase + (t & 1) * NB * HD);
            float4* dst = (float4*)(&h_s[0][0]);
            for (int i = tid; i < NB * HD / 4; i += 256)
                dst[i] = __ldcg(src + i);
        }
        __syncthreads();
    }

    // emit mp[b][u][dir*384 + j] = max(segmax, 0)  (accumulator init was 0)
    if (tid < 48) {
        for (int u = 1; u <= NU; u++)
            g_mp[(b_a * NU + (u - 1)) * HDIM + dir * HD + j0 + jj_a] =
                segmax_s[b_a][u][jj_a];
    }
}

// ---------------- K3: topic softmax routing ---------------------------------
__global__ void __launch_bounds__(256) k_route(
    const float* __restrict__ tw, const float* __restrict__ tb,
    const float* __restrict__ table)
{
    const int b = blockIdx.x >> 5;
    const int u = blockIdx.x & 31;
    __shared__ float mp_s[768];
    __shared__ float lp_s[4][64];
    __shared__ float l_s[64], e_s[64];
    const int tid = threadIdx.x;
    const float* mpr = g_mp + (b * NU + u) * HDIM;
    for (int i = tid; i < 192; i += 256)
        ((float4*)mp_s)[i] = ((const float4*)mpr)[i];
    __syncthreads();
    {
        const int topic = tid & 63, slice = tid >> 6;
        float acc = 0.f;
        const float* wr = tw + topic * 768 + slice * 192;
        const float* ms = mp_s + slice * 192;
        for (int k = 0; k < 192; k += 4) {
            float4 wv = *(const float4*)(wr + k);
            acc = fmaf(wv.x, ms[k], acc);
            acc = fmaf(wv.y, ms[k + 1], acc);
            acc = fmaf(wv.z, ms[k + 2], acc);
            acc = fmaf(wv.w, ms[k + 3], acc);
        }
        lp_s[slice][topic] = acc;
    }
    __syncthreads();
    if (tid < 64)
        l_s[tid] = lp_s[0][tid] + lp_s[1][tid] + lp_s[2][tid] + lp_s[3][tid] + tb[tid];
    __syncthreads();
    if (tid < 64) {
        float mx = -1e30f;
        for (int i = 0; i < 64; i++) mx = fmaxf(mx, l_s[i]);
        e_s[tid] = expf(l_s[tid] - mx);
    }
    __syncthreads();
    float ssum = 0.f;
    for (int i = 0; i < 64; i++) ssum += e_s[i];
    float inv = 1.f / ssum;
    for (int h = tid; h < 768; h += 256) {
        float acc = 0.f;
        for (int tt = 0; tt < 64; tt++)
            acc = fmaf(e_s[tt], table[tt * 768 + h], acc);
        g_emb[(b * NU + u) * HDIM + h] = acc * inv;
    }
}

// ---------------- K4: scatter back to token positions -----------------------
__global__ void __launch_bounds__(256) k_scatter(
    const int* __restrict__ utter, float* __restrict__ out)
{
    int v = blockIdx.x * 256 + threadIdx.x;   // one float4 per thread, exact grid
    int m = v / 192;                          // (b, s)
    int h4 = v - m * 192;
    int u = __ldg(utter + m);
    float4 o = make_float4(0.f, 0.f, 0.f, 0.f);
    if (u != 0) {
        int idx = u > 0 ? u - 1 : -u - 1;
        if (idx > 31) idx = 31;
        int bb = m >> 11;
        float4 gv = *(const float4*)(g_emb + (bb * NU + idx) * HDIM + h4 * 4);
        float sc = u > 0 ? 1.f : 2.f;
        o.x = gv.x * sc; o.y = gv.y * sc; o.z = gv.z * sc; o.w = gv.w * sc;
    }
    ((float4*)out)[v] = o;
}

// ---------------- launch -----------------------------------------------------
extern "C" void kernel_launch(void* const* d_in, const int* in_sizes, int n_in,
                              void* d_out, int out_size)
{
    const float* X     = (const float*)d_in[0];
    const float* Wihf  = (const float*)d_in[1];
    const float* Whhf  = (const float*)d_in[2];
    const float* bihf  = (const float*)d_in[3];
    const float* bhhf  = (const float*)d_in[4];
    const float* Wihb  = (const float*)d_in[5];
    const float* Whhb  = (const float*)d_in[6];
    const float* bihb  = (const float*)d_in[7];
    const float* bhhb  = (const float*)d_in[8];
    const float* tw    = (const float*)d_in[9];
    const float* tb    = (const float*)d_in[10];
    const float* table = (const float*)d_in[11];
    const int*   utter = (const int*)d_in[12];

    k_reset<<<16, 256>>>();
    k_gemm<<<dim3(12, 128, 2), 256>>>(X, Wihf, Wihb, bihf, bhhf, bihb, bhhb);
    k_lstm<<<128, 256>>>(Whhf, Whhb, utter);
    k_route<<<256, 256>>>(tw, tb, table);
    k_scatter<<<12288, 256>>>(utter, (float*)d_out);
}